// round 16
// baseline (speedup 1.0000x reference)
#include <cuda_runtime.h>
#include <cuda_bf16.h>
#include <math.h>
#include <stdint.h>

typedef unsigned long long u64;
typedef unsigned int u32;

#define BATCH 8
#define CIN 1024
#define CMID 512
#define HH 50
#define WW 50
#define HW 2500
#define NA 9
#define NANCH 22500
#define SEG 32768
#define PRE_N 2000
#define POST_N 100

#define TDIM 13
#define NTILE (TDIM * TDIM)  // 169
#define GMW (BATCH * NTILE)  // 1352
#define NPT 36
#define KSPLIT 2
#define KHALF (CIN / KSPLIT) // 512

__device__ float   g_t[(size_t)BATCH * HW * CMID];
__device__ float   g_U[(size_t)NPT * CMID * CIN];
__device__ float   g_V[(size_t)NPT * CIN * GMW];
__device__ float   g_M[(size_t)KSPLIT * NPT * GMW * CMID];   // 200 MB (2 partials)
__device__ float   g_boxes[(size_t)BATCH * NANCH * 4];
__device__ u64     g_keys[(size_t)BATCH * SEG];
__device__ float   g_topboxes[(size_t)BATCH * PRE_N * 4];
__device__ float   g_topscores[(size_t)BATCH * PRE_N];
__device__ u64     g_mask[(size_t)BATCH * PRE_N * 32];
__device__ u64     g_keep[BATCH * 32];

__device__ __forceinline__ u32 ordf(float f) {
    u32 b = __float_as_uint(f);
    return (b & 0x80000000u) ? ~b : (b | 0x80000000u);
}
__device__ __forceinline__ float unordf(u32 o) {
    u32 b = (o & 0x80000000u) ? (o ^ 0x80000000u) : ~o;
    return __uint_as_float(b);
}
__device__ __forceinline__ void fma2(u64& c, u64 a, u64 b) {
    asm("fma.rn.f32x2 %0, %1, %2, %0;" : "+l"(c) : "l"(a), "l"(b));
}
__device__ __forceinline__ void unpack2(u64 v, float& lo, float& hi) {
    asm("mov.b64 {%0, %1}, %2;" : "=f"(lo), "=f"(hi) : "l"(v));
}

// ---------------- F(4,3) weight transform ----------------
__global__ __launch_bounds__(256) void wgt_kernel(const float* __restrict__ W1,
                                                  float* __restrict__ U)
{
    int idx = blockIdx.x * 256 + threadIdx.x;
    if (idx >= CMID * CIN) return;
    int o = idx / CIN, c = idx - o * CIN;
    const float* g = W1 + ((size_t)o * CIN + c) * 9;
    float gm[3][3];
#pragma unroll
    for (int i = 0; i < 3; i++)
#pragma unroll
        for (int j = 0; j < 3; j++) gm[i][j] = g[i * 3 + j];
    float t[6][3];
    const float s6 = 1.f / 6.f, s12 = 1.f / 12.f, s24 = 1.f / 24.f;
#pragma unroll
    for (int j = 0; j < 3; j++) {
        float g0 = gm[0][j], g1 = gm[1][j], g2 = gm[2][j];
        t[0][j] = 0.25f * g0;
        t[1][j] = -s6 * (g0 + g1 + g2);
        t[2][j] = -s6 * (g0 - g1 + g2);
        t[3][j] = s24 * g0 + s12 * g1 + s6 * g2;
        t[4][j] = s24 * g0 - s12 * g1 + s6 * g2;
        t[5][j] = g2;
    }
#pragma unroll
    for (int i = 0; i < 6; i++) {
        float g0 = t[i][0], g1 = t[i][1], g2 = t[i][2];
        float r[6];
        r[0] = 0.25f * g0;
        r[1] = -s6 * (g0 + g1 + g2);
        r[2] = -s6 * (g0 - g1 + g2);
        r[3] = s24 * g0 + s12 * g1 + s6 * g2;
        r[4] = s24 * g0 - s12 * g1 + s6 * g2;
        r[5] = g2;
#pragma unroll
        for (int j = 0; j < 6; j++)
            U[((size_t)(i * 6 + j) * CMID + o) * CIN + c] = r[j];
    }
}

// ---------------- F(4,3) input transform ----------------
__global__ __launch_bounds__(128) void intrans_kernel(const float* __restrict__ feat,
                                                      float* __restrict__ V)
{
    __shared__ float pl[HH * WW];
    const int bid = blockIdx.x;
    const int b = bid >> 10, c = bid & 1023;
    const int tid = threadIdx.x;
    const float* src = feat + ((size_t)b * CIN + c) * HW;
    for (int i = tid; i < HW; i += 128) pl[i] = src[i];
    __syncthreads();

    for (int t = tid; t < NTILE; t += 128) {
        int ty = t / TDIM, tx = t - ty * TDIM;
        int iy0 = 4 * ty - 1, ix0 = 4 * tx - 1;
        float d[6][6];
#pragma unroll
        for (int i = 0; i < 6; i++) {
            int iy = iy0 + i;
#pragma unroll
            for (int j = 0; j < 6; j++) {
                int ix = ix0 + j;
                d[i][j] = ((unsigned)iy < HH && (unsigned)ix < WW) ? pl[iy * WW + ix] : 0.f;
            }
        }
        float tr[6][6];
#pragma unroll
        for (int j = 0; j < 6; j++) {
            float d0 = d[0][j], d1 = d[1][j], d2 = d[2][j], d3 = d[3][j], d4 = d[4][j], d5 = d[5][j];
            tr[0][j] = 4.f * d0 - 5.f * d2 + d4;
            tr[1][j] = -4.f * d1 - 4.f * d2 + d3 + d4;
            tr[2][j] = 4.f * d1 - 4.f * d2 - d3 + d4;
            tr[3][j] = -2.f * d1 - d2 + 2.f * d3 + d4;
            tr[4][j] = 2.f * d1 - d2 - 2.f * d3 + d4;
            tr[5][j] = 4.f * d1 - 5.f * d3 + d5;
        }
        int m = b * NTILE + t;
#pragma unroll
        for (int i = 0; i < 6; i++) {
            float d0 = tr[i][0], d1 = tr[i][1], d2 = tr[i][2], d3 = tr[i][3], d4 = tr[i][4], d5 = tr[i][5];
            V[((size_t)(i * 6 + 0) * CIN + c) * GMW + m] = 4.f * d0 - 5.f * d2 + d4;
            V[((size_t)(i * 6 + 1) * CIN + c) * GMW + m] = -4.f * d1 - 4.f * d2 + d3 + d4;
            V[((size_t)(i * 6 + 2) * CIN + c) * GMW + m] = 4.f * d1 - 4.f * d2 - d3 + d4;
            V[((size_t)(i * 6 + 3) * CIN + c) * GMW + m] = -2.f * d1 - d2 + 2.f * d3 + d4;
            V[((size_t)(i * 6 + 4) * CIN + c) * GMW + m] = 2.f * d1 - d2 - 2.f * d3 + d4;
            V[((size_t)(i * 6 + 5) * CIN + c) * GMW + m] = 4.f * d1 - 5.f * d3 + d5;
        }
    }
}

// ---------------- batched GEMM with deterministic split-K=2 ----------------
#define TM 128
#define TN 128
#define TK 16
__global__ __launch_bounds__(256, 2) void wino_gemm_kernel(
    const float* __restrict__ V, const float* __restrict__ U, float* __restrict__ M)
{
    __shared__ float As[TK][TM];
    __shared__ float Bs[TK][TN];

    const int m0 = blockIdx.x * TM;
    const int o0 = blockIdx.y * TN;
    const int zp = blockIdx.z;
    const int p  = zp >> 1;
    const int ks = zp & 1;
    const int kbeg = ks * KHALF, kend = kbeg + KHALF;
    const int tid = threadIdx.x;
    const int tx = tid & 15;
    const int ty = tid >> 4;

    const float* Vb = V + (size_t)p * CIN * GMW;

    int kkA[8];
#pragma unroll
    for (int it = 0; it < 8; it++) kkA[it] = (tid + it * 256) >> 7;
    const int mmA = tid & 127;
    const int mA = m0 + mmA;
    const bool mvA = mA < GMW;
    const int mAc = mvA ? mA : 0;
    const int ooB = tid >> 1;
    const int kqB = (tid & 1) * 8;
    const float* wrow = U + ((size_t)p * CMID + o0 + ooB) * CIN + kqB;

    u64 acc2[8][4];
#pragma unroll
    for (int i = 0; i < 8; i++)
#pragma unroll
        for (int j = 0; j < 4; j++) acc2[i][j] = 0ull;

    float pa[8];
    float4 pb0, pb1;

#pragma unroll
    for (int it = 0; it < 8; it++)
        pa[it] = mvA ? Vb[(size_t)(kbeg + kkA[it]) * GMW + mAc] : 0.f;
    pb0 = *reinterpret_cast<const float4*>(wrow + kbeg);
    pb1 = *reinterpret_cast<const float4*>(wrow + kbeg + 4);

    for (int k0 = kbeg; k0 < kend; k0 += TK) {
#pragma unroll
        for (int it = 0; it < 8; it++)
            As[kkA[it]][mmA] = pa[it];
        Bs[kqB + 0][ooB] = pb0.x; Bs[kqB + 1][ooB] = pb0.y;
        Bs[kqB + 2][ooB] = pb0.z; Bs[kqB + 3][ooB] = pb0.w;
        Bs[kqB + 4][ooB] = pb1.x; Bs[kqB + 5][ooB] = pb1.y;
        Bs[kqB + 6][ooB] = pb1.z; Bs[kqB + 7][ooB] = pb1.w;
        __syncthreads();

        if (k0 + TK < kend) {
            int kn = k0 + TK;
#pragma unroll
            for (int it = 0; it < 8; it++)
                pa[it] = mvA ? Vb[(size_t)(kn + kkA[it]) * GMW + mAc] : 0.f;
            pb0 = *reinterpret_cast<const float4*>(wrow + kn);
            pb1 = *reinterpret_cast<const float4*>(wrow + kn + 4);
        }

#pragma unroll
        for (int kk = 0; kk < TK; kk++) {
            float4 a0 = *reinterpret_cast<const float4*>(&As[kk][tx * 8]);
            float4 a1 = *reinterpret_cast<const float4*>(&As[kk][tx * 8 + 4]);
            u64 ad[8];
            asm("mov.b64 %0, {%1, %1};" : "=l"(ad[0]) : "f"(a0.x));
            asm("mov.b64 %0, {%1, %1};" : "=l"(ad[1]) : "f"(a0.y));
            asm("mov.b64 %0, {%1, %1};" : "=l"(ad[2]) : "f"(a0.z));
            asm("mov.b64 %0, {%1, %1};" : "=l"(ad[3]) : "f"(a0.w));
            asm("mov.b64 %0, {%1, %1};" : "=l"(ad[4]) : "f"(a1.x));
            asm("mov.b64 %0, {%1, %1};" : "=l"(ad[5]) : "f"(a1.y));
            asm("mov.b64 %0, {%1, %1};" : "=l"(ad[6]) : "f"(a1.z));
            asm("mov.b64 %0, {%1, %1};" : "=l"(ad[7]) : "f"(a1.w));
            const u64* brow = reinterpret_cast<const u64*>(&Bs[kk][ty * 8]);
            u64 bp0 = brow[0], bp1 = brow[1], bp2 = brow[2], bp3 = brow[3];
#pragma unroll
            for (int i = 0; i < 8; i++) {
                fma2(acc2[i][0], ad[i], bp0);
                fma2(acc2[i][1], ad[i], bp1);
                fma2(acc2[i][2], ad[i], bp2);
                fma2(acc2[i][3], ad[i], bp3);
            }
        }
        __syncthreads();
    }

#pragma unroll
    for (int i = 0; i < 8; i++) {
        int m = m0 + tx * 8 + i;
        if (m >= GMW) continue;
        float* row = M + (((size_t)ks * NPT + p) * GMW + m) * CMID + o0 + ty * 8;
#pragma unroll
        for (int j = 0; j < 4; j++) {
            float lo, hi;
            unpack2(acc2[i][j], lo, hi);
            float2 o;
            o.x = lo; o.y = hi;
            *reinterpret_cast<float2*>(row + j * 2) = o;
        }
    }
}

// ---------------- F(4,3) output transform (combines split-K partials) ----------------
__global__ __launch_bounds__(256) void outtrans_kernel(
    const float* __restrict__ M, const float* __restrict__ b1, float* __restrict__ out)
{
    int idx = blockIdx.x * 256 + threadIdx.x;
    if (idx >= GMW * CMID) return;
    int m = idx >> 9, o = idx & 511;
    int b = m / NTILE, tile = m - b * NTILE;
    int ty = tile / TDIM, tx = tile - ty * TDIM;

    const float* M0 = M;
    const float* M1 = M + (size_t)NPT * GMW * CMID;
    float mv[6][6];
#pragma unroll
    for (int p = 0; p < 36; p++) {
        size_t off = ((size_t)p * GMW + m) * CMID + o;
        mv[p / 6][p % 6] = M0[off] + M1[off];
    }

    float s[4][6];
#pragma unroll
    for (int j = 0; j < 6; j++) {
        float m0 = mv[0][j], m1 = mv[1][j], m2 = mv[2][j], m3 = mv[3][j], m4 = mv[4][j], m5 = mv[5][j];
        s[0][j] = m0 + m1 + m2 + m3 + m4;
        s[1][j] = m1 - m2 + 2.f * m3 - 2.f * m4;
        s[2][j] = m1 + m2 + 4.f * m3 + 4.f * m4;
        s[3][j] = m1 - m2 + 8.f * m3 - 8.f * m4 + m5;
    }
    float bias = b1[o];
    int Y0 = 4 * ty, X0 = 4 * tx;
#pragma unroll
    for (int i = 0; i < 4; i++) {
        float m0 = s[i][0], m1 = s[i][1], m2 = s[i][2], m3 = s[i][3], m4 = s[i][4], m5 = s[i][5];
        float y[4];
        y[0] = m0 + m1 + m2 + m3 + m4;
        y[1] = m1 - m2 + 2.f * m3 - 2.f * m4;
        y[2] = m1 + m2 + 4.f * m3 + 4.f * m4;
        y[3] = m1 - m2 + 8.f * m3 - 8.f * m4 + m5;
        int Y = Y0 + i;
        if (Y >= HH) continue;
#pragma unroll
        for (int j = 0; j < 4; j++) {
            int X = X0 + j;
            if (X >= WW) continue;
            float v = y[j] + bias;
            out[((size_t)b * HW + Y * WW + X) * CMID + o] = v > 0.f ? v : 0.f;
        }
    }
}

// ---------------- head: batched GEMV + decode ----------------
#define HB 64
__global__ __launch_bounds__(256) void head_kernel(
    const float* __restrict__ t, const float* __restrict__ W2, const float* __restrict__ b2,
    const float* __restrict__ W3, const float* __restrict__ b3,
    float* __restrict__ boxes_all, u64* __restrict__ keys)
{
    __shared__ float ts[HB][68];
    __shared__ float Ws[48][68];
    __shared__ float hv[HB][49];

    const int tid = threadIdx.x;
    const int p = tid >> 2;
    const int tj = tid & 3;
    const int pos0 = blockIdx.x * HB;

    float4 acc[12];
#pragma unroll
    for (int i = 0; i < 12; i++) acc[i] = make_float4(0.f, 0.f, 0.f, 0.f);

    const int pos_l = pos0 + p;
    const bool pv = pos_l < BATCH * HW;
    const float* trow = t + (size_t)(pv ? pos_l : 0) * CMID;

    for (int chunk = 0; chunk < 8; chunk++) {
        const int kbase = chunk * 64;
#pragma unroll
        for (int q = 0; q < 4; q++) {
            int k4 = tj + q * 4;
            float4 v = pv ? *reinterpret_cast<const float4*>(trow + kbase + k4 * 4)
                          : make_float4(0.f, 0.f, 0.f, 0.f);
            *reinterpret_cast<float4*>(&ts[p][k4 * 4]) = v;
        }
#pragma unroll
        for (int q = 0; q < 3; q++) {
            int idx = tid + q * 256;
            int o = idx >> 4, k4 = idx & 15;
            float4 v;
            if (o < 36)      v = *reinterpret_cast<const float4*>(W2 + (size_t)o * CMID + kbase + k4 * 4);
            else if (o < 45) v = *reinterpret_cast<const float4*>(W3 + (size_t)(o - 36) * CMID + kbase + k4 * 4);
            else             v = make_float4(0.f, 0.f, 0.f, 0.f);
            *reinterpret_cast<float4*>(&Ws[o][k4 * 4]) = v;
        }
        __syncthreads();

#pragma unroll
        for (int k4 = 0; k4 < 16; k4++) {
            float4 tv = *reinterpret_cast<const float4*>(&ts[p][k4 * 4]);
#pragma unroll
            for (int i = 0; i < 12; i++) {
                int o = tj + 4 * i;
                float4 wv = *reinterpret_cast<const float4*>(&Ws[o][k4 * 4]);
                acc[i].x += tv.x * wv.x;
                acc[i].y += tv.y * wv.y;
                acc[i].z += tv.z * wv.z;
                acc[i].w += tv.w * wv.w;
            }
        }
        __syncthreads();
    }

#pragma unroll
    for (int i = 0; i < 12; i++) {
        int o = tj + 4 * i;
        if (o < 45) {
            float bias = (o < 36) ? b2[o] : b3[o - 36];
            hv[p][o] = ((acc[i].x + acc[i].y) + (acc[i].z + acc[i].w)) + bias;
        }
    }
    __syncthreads();

    for (int e = tid; e < HB * NA; e += 256) {
        int pp = e / NA, a = e - pp * NA;
        int pos = pos0 + pp;
        if (pos >= BATCH * HW) continue;
        int b = pos / HW;
        int m = pos - b * HW;
        int y = m / WW, x = m - y * WW;

        const double areas[3] = {16384.0, 65536.0, 262144.0};
        const double ratios[3] = {0.5, 1.0, 2.0};
        int ia = a / 3, ir = a - ia * 3;
        float w = (float)sqrt(areas[ia] * ratios[ir]);
        float h = (float)sqrt(areas[ia] / ratios[ir]);

        float tx_ = hv[pp][a * 4 + 0];
        float ty_ = hv[pp][a * 4 + 1];
        float clip = (float)log(62.5);
        float tw_ = fminf(hv[pp][a * 4 + 2], clip);
        float th_ = fminf(hv[pp][a * 4 + 3], clip);
        float logit = hv[pp][36 + a];

        float cx = ((float)x + 0.5f) * 32.f;
        float cy = ((float)y + 0.5f) * 32.f;
        float x1 = cx - w * 0.5f, x2 = cx + w * 0.5f;
        float y1 = cy - h * 0.5f, y2 = cy + h * 0.5f;
        float wa = x2 - x1, ha = y2 - y1;
        float cxa = x1 + 0.5f * wa, cya = y1 + 0.5f * ha;

        float px = tx_ * wa + cxa;
        float py = ty_ * ha + cya;
        float pw = expf(tw_) * wa;
        float ph = expf(th_) * ha;

        float bx1 = fminf(fmaxf(px - pw * 0.5f, 0.f), 1600.f);
        float by1 = fminf(fmaxf(py - ph * 0.5f, 0.f), 1600.f);
        float bx2 = fminf(fmaxf(px + pw * 0.5f, 0.f), 1600.f);
        float by2 = fminf(fmaxf(py + ph * 0.5f, 0.f), 1600.f);

        float bw = bx2 - bx1, bh = by2 - by1;
        float score = 1.f / (1.f + expf(-logit));
        bool valid = (score >= 0.1f) && (bw > 16.f) && (bh > 16.f);
        float ms = valid ? score : -1.0f;

        int idx = m * NA + a;
        size_t bi = (size_t)b * NANCH + idx;
        boxes_all[bi * 4 + 0] = bx1;
        boxes_all[bi * 4 + 1] = by1;
        boxes_all[bi * 4 + 2] = bx2;
        boxes_all[bi * 4 + 3] = by2;
        keys[(size_t)b * SEG + idx] = ((u64)(~ordf(ms)) << 32) | (u32)idx;
    }
}

// ---------------- bitonic sort ----------------
__global__ __launch_bounds__(1024) void bsortA(u64* __restrict__ keys)
{
    if ((blockIdx.x & 7) >= 6) return;
    __shared__ u64 s[4096];
    const int cb = blockIdx.x * 4096;
    const int segb = cb & (SEG - 1);
    const int tid = threadIdx.x;
#pragma unroll
    for (int i = 0; i < 4; i++) s[tid + i * 1024] = keys[cb + tid + i * 1024];
    __syncthreads();
    for (int size = 2; size <= 4096; size <<= 1) {
        for (int stride = size >> 1; stride >= 1; stride >>= 1) {
#pragma unroll 1
            for (int t = tid; t < 2048; t += 1024) {
                int l = ((t & ~(stride - 1)) << 1) | (t & (stride - 1));
                int r = l | stride;
                bool up = (((l + segb) & size) == 0);
                u64 a = s[l], bk = s[r];
                if ((a > bk) == up) { s[l] = bk; s[r] = a; }
            }
            __syncthreads();
        }
    }
#pragma unroll
    for (int i = 0; i < 4; i++) keys[cb + tid + i * 1024] = s[tid + i * 1024];
}

__global__ __launch_bounds__(256) void bsortG(u64* __restrict__ keys, int size, int stride)
{
    int t = blockIdx.x * blockDim.x + threadIdx.x;
    int l = ((t & ~(stride - 1)) << 1) | (t & (stride - 1));
    int r = l | stride;
    bool up = (((l & (SEG - 1)) & size) == 0);
    u64 a = keys[l], bk = keys[r];
    if ((a > bk) == up) { keys[l] = bk; keys[r] = a; }
}

__global__ __launch_bounds__(1024) void bsortF(u64* __restrict__ keys, int size)
{
    __shared__ u64 s[4096];
    const int cb = blockIdx.x * 4096;
    const int segb = cb & (SEG - 1);
    const int tid = threadIdx.x;
#pragma unroll
    for (int i = 0; i < 4; i++) s[tid + i * 1024] = keys[cb + tid + i * 1024];
    __syncthreads();
    const bool up = ((segb & size) == 0);
    for (int stride = 2048; stride >= 1; stride >>= 1) {
#pragma unroll 1
        for (int t = tid; t < 2048; t += 1024) {
            int l = ((t & ~(stride - 1)) << 1) | (t & (stride - 1));
            int r = l | stride;
            u64 a = s[l], bk = s[r];
            if ((a > bk) == up) { s[l] = bk; s[r] = a; }
        }
        __syncthreads();
    }
#pragma unroll
    for (int i = 0; i < 4; i++) keys[cb + tid + i * 1024] = s[tid + i * 1024];
}

// ---------------- gather top-2000 ----------------
__global__ __launch_bounds__(256) void gather_kernel(
    const u64* __restrict__ keys, const float* __restrict__ boxes_all,
    float* __restrict__ topboxes, float* __restrict__ topscores)
{
    int t = blockIdx.x * blockDim.x + threadIdx.x;
    if (t >= BATCH * PRE_N) return;
    int seg = t / PRE_N, r = t - seg * PRE_N;
    u64 key = keys[(size_t)seg * SEG + r];
    u32 idx = (u32)(key & 0xFFFFFFFFu);
    topscores[t] = unordf(~(u32)(key >> 32));
    float4 bb = *reinterpret_cast<const float4*>(boxes_all + ((size_t)seg * NANCH + idx) * 4);
    *reinterpret_cast<float4*>(topboxes + (size_t)t * 4) = bb;
}

// ---------------- NMS ----------------
__device__ __forceinline__ bool iou_gt(float4 bi, float area_i, float4 bj)
{
    float area_j = (bj.z - bj.x) * (bj.w - bj.y);
    float ltx = fmaxf(bi.x, bj.x), lty = fmaxf(bi.y, bj.y);
    float rbx = fminf(bi.z, bj.z), rby = fminf(bi.w, bj.w);
    float wx = fmaxf(rbx - ltx, 0.f), wy = fmaxf(rby - lty, 0.f);
    float inter = wx * wy;
    return inter / (area_i + area_j - inter + 1e-9f) > 0.7f;
}

__global__ __launch_bounds__(256) void mask_kernel(
    const float* __restrict__ topboxes, u64* __restrict__ masks)
{
    int row = blockIdx.x * 8 + (threadIdx.x >> 5);
    int lane = threadIdx.x & 31;
    int seg = row / PRE_N, i = row - seg * PRE_N;
    const float* B = topboxes + (size_t)seg * PRE_N * 4;
    float4 bi = *reinterpret_cast<const float4*>(B + (size_t)i * 4);
    float area_i = (bi.z - bi.x) * (bi.w - bi.y);
    u64* mrow = masks + (size_t)row * 32;
    const int w0 = i >> 6;                 // words below diagonal are all-zero
    for (int w = lane; w < w0; w += 32) mrow[w] = 0ULL;
    for (int w = w0; w < 32; w++) {
        int j0 = w * 64;
        bool p0 = false, p1 = false;
        int j = j0 + lane;
        if (j < PRE_N && j > i)
            p0 = iou_gt(bi, area_i, *reinterpret_cast<const float4*>(B + (size_t)j * 4));
        j = j0 + 32 + lane;
        if (j < PRE_N && j > i)
            p1 = iou_gt(bi, area_i, *reinterpret_cast<const float4*>(B + (size_t)j * 4));
        u32 lo = __ballot_sync(0xFFFFFFFFu, p0);
        u32 hi = __ballot_sync(0xFFFFFFFFu, p1);
        if (lane == 0) mrow[w] = ((u64)hi << 32) | lo;
    }
}

__global__ __launch_bounds__(256) void scan_kernel(
    const float* __restrict__ topscores, const u64* __restrict__ masks, u64* __restrict__ keep)
{
    const int seg = blockIdx.x;
    __shared__ u64 buf[64 * 32];
    const int tid = threadIdx.x;
    const int lane = tid & 31, wid = tid >> 5;

    u64 keepw = 0;
    if (wid == 0) {
        for (int bbit = 0; bbit < 64; bbit++) {
            int i = lane * 64 + bbit;
            if (i < PRE_N && topscores[seg * PRE_N + i] > 0.f) keepw |= 1ULL << bbit;
        }
    }
    const u64* mseg = masks + (size_t)seg * PRE_N * 32;
    for (int c = 0; c < 32; c++) {
        __syncthreads();
        int r0 = c * 64;
        for (int e = tid; e < 64 * 32; e += 256) {
            int rr = e >> 5, wwi = e & 31;
            int row = r0 + rr;
            buf[e] = (row < PRE_N) ? mseg[(size_t)row * 32 + wwi] : 0ULL;
        }
        __syncthreads();
        if (wid == 0) {
            int n = PRE_N - r0; if (n > 64) n = 64;
            for (int r = 0; r < n; r++) {
                u64 kw = __shfl_sync(0xFFFFFFFFu, keepw, c);
                if ((kw >> r) & 1ULL) keepw &= ~buf[r * 32 + lane];
            }
        }
    }
    __syncthreads();
    if (wid == 0) keep[seg * 32 + lane] = keepw;
}

__global__ __launch_bounds__(1024) void post_kernel(
    const float* __restrict__ topscores, const float* __restrict__ topboxes,
    const u64* __restrict__ keepbits, float* __restrict__ out)
{
    const int seg = blockIdx.x;
    __shared__ u64 s[2048];
    const int tid = threadIdx.x;
    for (int i = tid; i < 2048; i += 1024) {
        u64 key;
        if (i < PRE_N) {
            float sc = topscores[seg * PRE_N + i];
            int kept = (int)((keepbits[seg * 32 + (i >> 6)] >> (i & 63)) & 1ULL);
            float ms = kept ? sc : -1.0f;
            key = ((u64)(~ordf(ms)) << 32) | (u32)i;
        } else key = ~0ULL;
        s[i] = key;
    }
    __syncthreads();
    for (int size = 2; size <= 2048; size <<= 1)
        for (int stride = size >> 1; stride >= 1; stride >>= 1) {
            int l = ((tid & ~(stride - 1)) << 1) | (tid & (stride - 1));
            int r = l | stride;
            bool up = ((l & size) == 0);
            u64 a = s[l], bk = s[r];
            if ((a > bk) == up) { s[l] = bk; s[r] = a; }
            __syncthreads();
        }
    if (tid < POST_N) {
        u64 key = s[tid];
        u32 idx = (u32)(key & 0xFFFFFFFFu);
        float sc = unordf(~(u32)(key >> 32));
        float4 bb = *reinterpret_cast<const float4*>(topboxes + ((size_t)seg * PRE_N + idx) * 4);
        float* ob = out + ((size_t)seg * POST_N + tid) * 4;
        ob[0] = bb.x; ob[1] = bb.y; ob[2] = bb.z; ob[3] = bb.w;
        out[BATCH * POST_N * 4 + seg * POST_N + tid] = sc;
    }
}

// ---------------- launch ----------------
extern "C" void kernel_launch(void* const* d_in, const int* in_sizes, int n_in,
                              void* d_out, int out_size)
{
    const float* feat = (const float*)d_in[0];
    const float* W1   = (const float*)d_in[1];
    const float* b1   = (const float*)d_in[2];
    const float* W2   = (const float*)d_in[3];
    const float* b2   = (const float*)d_in[4];
    const float* W3   = (const float*)d_in[5];
    const float* b3   = (const float*)d_in[6];
    float* out = (float*)d_out;

    float *t_ptr, *boxes_ptr, *tb_ptr, *ts_ptr, *U_ptr, *V_ptr, *M_ptr;
    u64 *keys_ptr, *mask_ptr, *keep_ptr;
    cudaGetSymbolAddress((void**)&t_ptr, g_t);
    cudaGetSymbolAddress((void**)&U_ptr, g_U);
    cudaGetSymbolAddress((void**)&V_ptr, g_V);
    cudaGetSymbolAddress((void**)&M_ptr, g_M);
    cudaGetSymbolAddress((void**)&boxes_ptr, g_boxes);
    cudaGetSymbolAddress((void**)&keys_ptr, g_keys);
    cudaGetSymbolAddress((void**)&tb_ptr, g_topboxes);
    cudaGetSymbolAddress((void**)&ts_ptr, g_topscores);
    cudaGetSymbolAddress((void**)&mask_ptr, g_mask);
    cudaGetSymbolAddress((void**)&keep_ptr, g_keep);

    // 1. winograd F(4,3) conv with split-K=2
    wgt_kernel<<<(CMID * CIN + 255) / 256, 256>>>(W1, U_ptr);
    intrans_kernel<<<BATCH * CIN, 128>>>(feat, V_ptr);
    dim3 ggrid((GMW + TM - 1) / TM, CMID / TN, NPT * KSPLIT);   // 11 x 4 x 72 = 3168 CTAs
    wino_gemm_kernel<<<ggrid, 256>>>(V_ptr, U_ptr, M_ptr);
    outtrans_kernel<<<(GMW * CMID + 255) / 256, 256>>>(M_ptr, b1, t_ptr);

    // 2. pad keys, then batched head GEMM + decode
    cudaMemsetAsync(keys_ptr, 0xFF, (size_t)BATCH * SEG * sizeof(u64));
    head_kernel<<<(BATCH * HW + HB - 1) / HB, 256>>>(t_ptr, W2, b2, W3, b3, boxes_ptr, keys_ptr);

    // 3. per-segment bitonic sort
    bsortA<<<BATCH * SEG / 4096, 1024>>>(keys_ptr);
    bsortG<<<512, 256>>>(keys_ptr, 8192, 4096);
    bsortF<<<BATCH * SEG / 4096, 1024>>>(keys_ptr, 8192);
    bsortG<<<512, 256>>>(keys_ptr, 16384, 8192);
    bsortG<<<512, 256>>>(keys_ptr, 16384, 4096);
    bsortF<<<BATCH * SEG / 4096, 1024>>>(keys_ptr, 16384);
    bsortG<<<512, 256>>>(keys_ptr, 32768, 16384);
    bsortG<<<512, 256>>>(keys_ptr, 32768, 8192);
    bsortG<<<512, 256>>>(keys_ptr, 32768, 4096);
    bsortF<<<BATCH * SEG / 4096, 1024>>>(keys_ptr, 32768);

    // 4-6. gather, NMS, output
    gather_kernel<<<(BATCH * PRE_N + 255) / 256, 256>>>(keys_ptr, boxes_ptr, tb_ptr, ts_ptr);
    mask_kernel<<<BATCH * PRE_N / 8, 256>>>(tb_ptr, mask_ptr);
    scan_kernel<<<BATCH, 256>>>(ts_ptr, mask_ptr, keep_ptr);
    post_kernel<<<BATCH, 1024>>>(ts_ptr, tb_ptr, keep_ptr, out);
}

// round 17
// speedup vs baseline: 1.0738x; 1.0738x over previous
#include <cuda_runtime.h>
#include <cuda_bf16.h>
#include <math.h>
#include <stdint.h>

typedef unsigned long long u64;
typedef unsigned int u32;

#define BATCH 8
#define CIN 1024
#define CMID 512
#define HH 50
#define WW 50
#define HW 2500
#define NA 9
#define NANCH 22500
#define SEG 32768
#define PRE_N 2000
#define POST_N 100

#define TDIM 13
#define NTILE (TDIM * TDIM)  // 169
#define GMW (BATCH * NTILE)  // 1352
#define NPT 36

__device__ float   g_t[(size_t)BATCH * HW * CMID];
__device__ float   g_U[(size_t)NPT * CMID * CIN];
__device__ float   g_V[(size_t)NPT * CIN * GMW];
__device__ float   g_M[(size_t)NPT * GMW * CMID];
__device__ float   g_boxes[(size_t)BATCH * NANCH * 4];
__device__ u64     g_keys[(size_t)BATCH * SEG];
__device__ float   g_topboxes[(size_t)BATCH * PRE_N * 4];
__device__ float   g_topscores[(size_t)BATCH * PRE_N];
__device__ u64     g_mask[(size_t)BATCH * PRE_N * 32];
__device__ u64     g_keep[BATCH * 32];

__device__ __forceinline__ u32 ordf(float f) {
    u32 b = __float_as_uint(f);
    return (b & 0x80000000u) ? ~b : (b | 0x80000000u);
}
__device__ __forceinline__ float unordf(u32 o) {
    u32 b = (o & 0x80000000u) ? (o ^ 0x80000000u) : ~o;
    return __uint_as_float(b);
}
__device__ __forceinline__ void fma2(u64& c, u64 a, u64 b) {
    asm("fma.rn.f32x2 %0, %1, %2, %0;" : "+l"(c) : "l"(a), "l"(b));
}
__device__ __forceinline__ void unpack2(u64 v, float& lo, float& hi) {
    asm("mov.b64 {%0, %1}, %2;" : "=f"(lo), "=f"(hi) : "l"(v));
}

// ---------------- F(4,3) weight transform ----------------
__global__ __launch_bounds__(256) void wgt_kernel(const float* __restrict__ W1,
                                                  float* __restrict__ U)
{
    int idx = blockIdx.x * 256 + threadIdx.x;
    if (idx >= CMID * CIN) return;
    int o = idx / CIN, c = idx - o * CIN;
    const float* g = W1 + ((size_t)o * CIN + c) * 9;
    float gm[3][3];
#pragma unroll
    for (int i = 0; i < 3; i++)
#pragma unroll
        for (int j = 0; j < 3; j++) gm[i][j] = g[i * 3 + j];
    float t[6][3];
    const float s6 = 1.f / 6.f, s12 = 1.f / 12.f, s24 = 1.f / 24.f;
#pragma unroll
    for (int j = 0; j < 3; j++) {
        float g0 = gm[0][j], g1 = gm[1][j], g2 = gm[2][j];
        t[0][j] = 0.25f * g0;
        t[1][j] = -s6 * (g0 + g1 + g2);
        t[2][j] = -s6 * (g0 - g1 + g2);
        t[3][j] = s24 * g0 + s12 * g1 + s6 * g2;
        t[4][j] = s24 * g0 - s12 * g1 + s6 * g2;
        t[5][j] = g2;
    }
#pragma unroll
    for (int i = 0; i < 6; i++) {
        float g0 = t[i][0], g1 = t[i][1], g2 = t[i][2];
        float r[6];
        r[0] = 0.25f * g0;
        r[1] = -s6 * (g0 + g1 + g2);
        r[2] = -s6 * (g0 - g1 + g2);
        r[3] = s24 * g0 + s12 * g1 + s6 * g2;
        r[4] = s24 * g0 - s12 * g1 + s6 * g2;
        r[5] = g2;
#pragma unroll
        for (int j = 0; j < 6; j++)
            U[((size_t)(i * 6 + j) * CMID + o) * CIN + c] = r[j];
    }
}

// ---------------- F(4,3) input transform ----------------
__global__ __launch_bounds__(128) void intrans_kernel(const float* __restrict__ feat,
                                                      float* __restrict__ V)
{
    __shared__ float pl[HH * WW];
    const int bid = blockIdx.x;
    const int b = bid >> 10, c = bid & 1023;
    const int tid = threadIdx.x;
    const float* src = feat + ((size_t)b * CIN + c) * HW;
    for (int i = tid; i < HW; i += 128) pl[i] = src[i];
    __syncthreads();

    for (int t = tid; t < NTILE; t += 128) {
        int ty = t / TDIM, tx = t - ty * TDIM;
        int iy0 = 4 * ty - 1, ix0 = 4 * tx - 1;
        float d[6][6];
#pragma unroll
        for (int i = 0; i < 6; i++) {
            int iy = iy0 + i;
#pragma unroll
            for (int j = 0; j < 6; j++) {
                int ix = ix0 + j;
                d[i][j] = ((unsigned)iy < HH && (unsigned)ix < WW) ? pl[iy * WW + ix] : 0.f;
            }
        }
        float tr[6][6];
#pragma unroll
        for (int j = 0; j < 6; j++) {
            float d0 = d[0][j], d1 = d[1][j], d2 = d[2][j], d3 = d[3][j], d4 = d[4][j], d5 = d[5][j];
            tr[0][j] = 4.f * d0 - 5.f * d2 + d4;
            tr[1][j] = -4.f * d1 - 4.f * d2 + d3 + d4;
            tr[2][j] = 4.f * d1 - 4.f * d2 - d3 + d4;
            tr[3][j] = -2.f * d1 - d2 + 2.f * d3 + d4;
            tr[4][j] = 2.f * d1 - d2 - 2.f * d3 + d4;
            tr[5][j] = 4.f * d1 - 5.f * d3 + d5;
        }
        int m = b * NTILE + t;
#pragma unroll
        for (int i = 0; i < 6; i++) {
            float d0 = tr[i][0], d1 = tr[i][1], d2 = tr[i][2], d3 = tr[i][3], d4 = tr[i][4], d5 = tr[i][5];
            V[((size_t)(i * 6 + 0) * CIN + c) * GMW + m] = 4.f * d0 - 5.f * d2 + d4;
            V[((size_t)(i * 6 + 1) * CIN + c) * GMW + m] = -4.f * d1 - 4.f * d2 + d3 + d4;
            V[((size_t)(i * 6 + 2) * CIN + c) * GMW + m] = 4.f * d1 - 4.f * d2 - d3 + d4;
            V[((size_t)(i * 6 + 3) * CIN + c) * GMW + m] = -2.f * d1 - d2 + 2.f * d3 + d4;
            V[((size_t)(i * 6 + 4) * CIN + c) * GMW + m] = 2.f * d1 - d2 - 2.f * d3 + d4;
            V[((size_t)(i * 6 + 5) * CIN + c) * GMW + m] = 4.f * d1 - 5.f * d3 + d5;
        }
    }
}

// ---------------- batched GEMM (R15 config, no split-K) ----------------
#define TM 128
#define TN 128
#define TK 16
__global__ __launch_bounds__(256, 2) void wino_gemm_kernel(
    const float* __restrict__ V, const float* __restrict__ U, float* __restrict__ M)
{
    __shared__ float As[TK][TM];
    __shared__ float Bs[TK][TN];

    const int m0 = blockIdx.x * TM;
    const int o0 = blockIdx.y * TN;
    const int p  = blockIdx.z;
    const int tid = threadIdx.x;
    const int tx = tid & 15;
    const int ty = tid >> 4;

    const float* Vb = V + (size_t)p * CIN * GMW;

    int kkA[8];
#pragma unroll
    for (int it = 0; it < 8; it++) kkA[it] = (tid + it * 256) >> 7;
    const int mmA = tid & 127;
    const int mA = m0 + mmA;
    const bool mvA = mA < GMW;
    const int mAc = mvA ? mA : 0;
    const int ooB = tid >> 1;
    const int kqB = (tid & 1) * 8;
    const float* wrow = U + ((size_t)p * CMID + o0 + ooB) * CIN + kqB;

    u64 acc2[8][4];
#pragma unroll
    for (int i = 0; i < 8; i++)
#pragma unroll
        for (int j = 0; j < 4; j++) acc2[i][j] = 0ull;

    float pa[8];
    float4 pb0, pb1;

#pragma unroll
    for (int it = 0; it < 8; it++)
        pa[it] = mvA ? Vb[(size_t)kkA[it] * GMW + mAc] : 0.f;
    pb0 = *reinterpret_cast<const float4*>(wrow);
    pb1 = *reinterpret_cast<const float4*>(wrow + 4);

    for (int k0 = 0; k0 < CIN; k0 += TK) {
#pragma unroll
        for (int it = 0; it < 8; it++)
            As[kkA[it]][mmA] = pa[it];
        Bs[kqB + 0][ooB] = pb0.x; Bs[kqB + 1][ooB] = pb0.y;
        Bs[kqB + 2][ooB] = pb0.z; Bs[kqB + 3][ooB] = pb0.w;
        Bs[kqB + 4][ooB] = pb1.x; Bs[kqB + 5][ooB] = pb1.y;
        Bs[kqB + 6][ooB] = pb1.z; Bs[kqB + 7][ooB] = pb1.w;
        __syncthreads();

        if (k0 + TK < CIN) {
            int kn = k0 + TK;
#pragma unroll
            for (int it = 0; it < 8; it++)
                pa[it] = mvA ? Vb[(size_t)(kn + kkA[it]) * GMW + mAc] : 0.f;
            pb0 = *reinterpret_cast<const float4*>(wrow + kn);
            pb1 = *reinterpret_cast<const float4*>(wrow + kn + 4);
        }

#pragma unroll
        for (int kk = 0; kk < TK; kk++) {
            float4 a0 = *reinterpret_cast<const float4*>(&As[kk][tx * 8]);
            float4 a1 = *reinterpret_cast<const float4*>(&As[kk][tx * 8 + 4]);
            u64 ad[8];
            asm("mov.b64 %0, {%1, %1};" : "=l"(ad[0]) : "f"(a0.x));
            asm("mov.b64 %0, {%1, %1};" : "=l"(ad[1]) : "f"(a0.y));
            asm("mov.b64 %0, {%1, %1};" : "=l"(ad[2]) : "f"(a0.z));
            asm("mov.b64 %0, {%1, %1};" : "=l"(ad[3]) : "f"(a0.w));
            asm("mov.b64 %0, {%1, %1};" : "=l"(ad[4]) : "f"(a1.x));
            asm("mov.b64 %0, {%1, %1};" : "=l"(ad[5]) : "f"(a1.y));
            asm("mov.b64 %0, {%1, %1};" : "=l"(ad[6]) : "f"(a1.z));
            asm("mov.b64 %0, {%1, %1};" : "=l"(ad[7]) : "f"(a1.w));
            const u64* brow = reinterpret_cast<const u64*>(&Bs[kk][ty * 8]);
            u64 bp0 = brow[0], bp1 = brow[1], bp2 = brow[2], bp3 = brow[3];
#pragma unroll
            for (int i = 0; i < 8; i++) {
                fma2(acc2[i][0], ad[i], bp0);
                fma2(acc2[i][1], ad[i], bp1);
                fma2(acc2[i][2], ad[i], bp2);
                fma2(acc2[i][3], ad[i], bp3);
            }
        }
        __syncthreads();
    }

#pragma unroll
    for (int i = 0; i < 8; i++) {
        int m = m0 + tx * 8 + i;
        if (m >= GMW) continue;
        float* row = M + ((size_t)p * GMW + m) * CMID + o0 + ty * 8;
#pragma unroll
        for (int j = 0; j < 4; j++) {
            float lo, hi;
            unpack2(acc2[i][j], lo, hi);
            float2 o;
            o.x = lo; o.y = hi;
            *reinterpret_cast<float2*>(row + j * 2) = o;
        }
    }
}

// ---------------- F(4,3) output transform ----------------
__global__ __launch_bounds__(256) void outtrans_kernel(
    const float* __restrict__ M, const float* __restrict__ b1, float* __restrict__ out)
{
    int idx = blockIdx.x * 256 + threadIdx.x;
    if (idx >= GMW * CMID) return;
    int m = idx >> 9, o = idx & 511;
    int b = m / NTILE, tile = m - b * NTILE;
    int ty = tile / TDIM, tx = tile - ty * TDIM;

    float mv[6][6];
#pragma unroll
    for (int p = 0; p < 36; p++)
        mv[p / 6][p % 6] = M[((size_t)p * GMW + m) * CMID + o];

    float s[4][6];
#pragma unroll
    for (int j = 0; j < 6; j++) {
        float m0 = mv[0][j], m1 = mv[1][j], m2 = mv[2][j], m3 = mv[3][j], m4 = mv[4][j], m5 = mv[5][j];
        s[0][j] = m0 + m1 + m2 + m3 + m4;
        s[1][j] = m1 - m2 + 2.f * m3 - 2.f * m4;
        s[2][j] = m1 + m2 + 4.f * m3 + 4.f * m4;
        s[3][j] = m1 - m2 + 8.f * m3 - 8.f * m4 + m5;
    }
    float bias = b1[o];
    int Y0 = 4 * ty, X0 = 4 * tx;
#pragma unroll
    for (int i = 0; i < 4; i++) {
        float m0 = s[i][0], m1 = s[i][1], m2 = s[i][2], m3 = s[i][3], m4 = s[i][4], m5 = s[i][5];
        float y[4];
        y[0] = m0 + m1 + m2 + m3 + m4;
        y[1] = m1 - m2 + 2.f * m3 - 2.f * m4;
        y[2] = m1 + m2 + 4.f * m3 + 4.f * m4;
        y[3] = m1 - m2 + 8.f * m3 - 8.f * m4 + m5;
        int Y = Y0 + i;
        if (Y >= HH) continue;
#pragma unroll
        for (int j = 0; j < 4; j++) {
            int X = X0 + j;
            if (X >= WW) continue;
            float v = y[j] + bias;
            out[((size_t)b * HW + Y * WW + X) * CMID + o] = v > 0.f ? v : 0.f;
        }
    }
}

// ---------------- head: batched GEMV + decode ----------------
#define HB 64
__global__ __launch_bounds__(256) void head_kernel(
    const float* __restrict__ t, const float* __restrict__ W2, const float* __restrict__ b2,
    const float* __restrict__ W3, const float* __restrict__ b3,
    float* __restrict__ boxes_all, u64* __restrict__ keys)
{
    __shared__ float ts[HB][68];
    __shared__ float Ws[48][68];
    __shared__ float hv[HB][49];

    const int tid = threadIdx.x;
    const int p = tid >> 2;
    const int tj = tid & 3;
    const int pos0 = blockIdx.x * HB;

    float4 acc[12];
#pragma unroll
    for (int i = 0; i < 12; i++) acc[i] = make_float4(0.f, 0.f, 0.f, 0.f);

    const int pos_l = pos0 + p;
    const bool pv = pos_l < BATCH * HW;
    const float* trow = t + (size_t)(pv ? pos_l : 0) * CMID;

    for (int chunk = 0; chunk < 8; chunk++) {
        const int kbase = chunk * 64;
#pragma unroll
        for (int q = 0; q < 4; q++) {
            int k4 = tj + q * 4;
            float4 v = pv ? *reinterpret_cast<const float4*>(trow + kbase + k4 * 4)
                          : make_float4(0.f, 0.f, 0.f, 0.f);
            *reinterpret_cast<float4*>(&ts[p][k4 * 4]) = v;
        }
#pragma unroll
        for (int q = 0; q < 3; q++) {
            int idx = tid + q * 256;
            int o = idx >> 4, k4 = idx & 15;
            float4 v;
            if (o < 36)      v = *reinterpret_cast<const float4*>(W2 + (size_t)o * CMID + kbase + k4 * 4);
            else if (o < 45) v = *reinterpret_cast<const float4*>(W3 + (size_t)(o - 36) * CMID + kbase + k4 * 4);
            else             v = make_float4(0.f, 0.f, 0.f, 0.f);
            *reinterpret_cast<float4*>(&Ws[o][k4 * 4]) = v;
        }
        __syncthreads();

#pragma unroll
        for (int k4 = 0; k4 < 16; k4++) {
            float4 tv = *reinterpret_cast<const float4*>(&ts[p][k4 * 4]);
#pragma unroll
            for (int i = 0; i < 12; i++) {
                int o = tj + 4 * i;
                float4 wv = *reinterpret_cast<const float4*>(&Ws[o][k4 * 4]);
                acc[i].x += tv.x * wv.x;
                acc[i].y += tv.y * wv.y;
                acc[i].z += tv.z * wv.z;
                acc[i].w += tv.w * wv.w;
            }
        }
        __syncthreads();
    }

#pragma unroll
    for (int i = 0; i < 12; i++) {
        int o = tj + 4 * i;
        if (o < 45) {
            float bias = (o < 36) ? b2[o] : b3[o - 36];
            hv[p][o] = ((acc[i].x + acc[i].y) + (acc[i].z + acc[i].w)) + bias;
        }
    }
    __syncthreads();

    for (int e = tid; e < HB * NA; e += 256) {
        int pp = e / NA, a = e - pp * NA;
        int pos = pos0 + pp;
        if (pos >= BATCH * HW) continue;
        int b = pos / HW;
        int m = pos - b * HW;
        int y = m / WW, x = m - y * WW;

        const double areas[3] = {16384.0, 65536.0, 262144.0};
        const double ratios[3] = {0.5, 1.0, 2.0};
        int ia = a / 3, ir = a - ia * 3;
        float w = (float)sqrt(areas[ia] * ratios[ir]);
        float h = (float)sqrt(areas[ia] / ratios[ir]);

        float tx_ = hv[pp][a * 4 + 0];
        float ty_ = hv[pp][a * 4 + 1];
        float clip = (float)log(62.5);
        float tw_ = fminf(hv[pp][a * 4 + 2], clip);
        float th_ = fminf(hv[pp][a * 4 + 3], clip);
        float logit = hv[pp][36 + a];

        float cx = ((float)x + 0.5f) * 32.f;
        float cy = ((float)y + 0.5f) * 32.f;
        float x1 = cx - w * 0.5f, x2 = cx + w * 0.5f;
        float y1 = cy - h * 0.5f, y2 = cy + h * 0.5f;
        float wa = x2 - x1, ha = y2 - y1;
        float cxa = x1 + 0.5f * wa, cya = y1 + 0.5f * ha;

        float px = tx_ * wa + cxa;
        float py = ty_ * ha + cya;
        float pw = expf(tw_) * wa;
        float ph = expf(th_) * ha;

        float bx1 = fminf(fmaxf(px - pw * 0.5f, 0.f), 1600.f);
        float by1 = fminf(fmaxf(py - ph * 0.5f, 0.f), 1600.f);
        float bx2 = fminf(fmaxf(px + pw * 0.5f, 0.f), 1600.f);
        float by2 = fminf(fmaxf(py + ph * 0.5f, 0.f), 1600.f);

        float bw = bx2 - bx1, bh = by2 - by1;
        float score = 1.f / (1.f + expf(-logit));
        bool valid = (score >= 0.1f) && (bw > 16.f) && (bh > 16.f);
        float ms = valid ? score : -1.0f;

        int idx = m * NA + a;
        size_t bi = (size_t)b * NANCH + idx;
        boxes_all[bi * 4 + 0] = bx1;
        boxes_all[bi * 4 + 1] = by1;
        boxes_all[bi * 4 + 2] = bx2;
        boxes_all[bi * 4 + 3] = by2;
        keys[(size_t)b * SEG + idx] = ((u64)(~ordf(ms)) << 32) | (u32)idx;
    }
}

// ---------------- bitonic sort ----------------
__global__ __launch_bounds__(1024) void bsortA(u64* __restrict__ keys)
{
    if ((blockIdx.x & 7) >= 6) return;
    __shared__ u64 s[4096];
    const int cb = blockIdx.x * 4096;
    const int segb = cb & (SEG - 1);
    const int tid = threadIdx.x;
#pragma unroll
    for (int i = 0; i < 4; i++) s[tid + i * 1024] = keys[cb + tid + i * 1024];
    __syncthreads();
    for (int size = 2; size <= 4096; size <<= 1) {
        for (int stride = size >> 1; stride >= 1; stride >>= 1) {
#pragma unroll 1
            for (int t = tid; t < 2048; t += 1024) {
                int l = ((t & ~(stride - 1)) << 1) | (t & (stride - 1));
                int r = l | stride;
                bool up = (((l + segb) & size) == 0);
                u64 a = s[l], bk = s[r];
                if ((a > bk) == up) { s[l] = bk; s[r] = a; }
            }
            __syncthreads();
        }
    }
#pragma unroll
    for (int i = 0; i < 4; i++) keys[cb + tid + i * 1024] = s[tid + i * 1024];
}

__global__ __launch_bounds__(256) void bsortG(u64* __restrict__ keys, int size, int stride)
{
    int t = blockIdx.x * blockDim.x + threadIdx.x;
    int l = ((t & ~(stride - 1)) << 1) | (t & (stride - 1));
    int r = l | stride;
    bool up = (((l & (SEG - 1)) & size) == 0);
    u64 a = keys[l], bk = keys[r];
    if ((a > bk) == up) { keys[l] = bk; keys[r] = a; }
}

__global__ __launch_bounds__(1024) void bsortF(u64* __restrict__ keys, int size)
{
    __shared__ u64 s[4096];
    const int cb = blockIdx.x * 4096;
    const int segb = cb & (SEG - 1);
    const int tid = threadIdx.x;
#pragma unroll
    for (int i = 0; i < 4; i++) s[tid + i * 1024] = keys[cb + tid + i * 1024];
    __syncthreads();
    const bool up = ((segb & size) == 0);
    for (int stride = 2048; stride >= 1; stride >>= 1) {
#pragma unroll 1
        for (int t = tid; t < 2048; t += 1024) {
            int l = ((t & ~(stride - 1)) << 1) | (t & (stride - 1));
            int r = l | stride;
            u64 a = s[l], bk = s[r];
            if ((a > bk) == up) { s[l] = bk; s[r] = a; }
        }
        __syncthreads();
    }
#pragma unroll
    for (int i = 0; i < 4; i++) keys[cb + tid + i * 1024] = s[tid + i * 1024];
}

// ---------------- gather top-2000 ----------------
__global__ __launch_bounds__(256) void gather_kernel(
    const u64* __restrict__ keys, const float* __restrict__ boxes_all,
    float* __restrict__ topboxes, float* __restrict__ topscores)
{
    int t = blockIdx.x * blockDim.x + threadIdx.x;
    if (t >= BATCH * PRE_N) return;
    int seg = t / PRE_N, r = t - seg * PRE_N;
    u64 key = keys[(size_t)seg * SEG + r];
    u32 idx = (u32)(key & 0xFFFFFFFFu);
    topscores[t] = unordf(~(u32)(key >> 32));
    float4 bb = *reinterpret_cast<const float4*>(boxes_all + ((size_t)seg * NANCH + idx) * 4);
    *reinterpret_cast<float4*>(topboxes + (size_t)t * 4) = bb;
}

// ---------------- NMS ----------------
__device__ __forceinline__ bool iou_gt(float4 bi, float area_i, float4 bj)
{
    float area_j = (bj.z - bj.x) * (bj.w - bj.y);
    float ltx = fmaxf(bi.x, bj.x), lty = fmaxf(bi.y, bj.y);
    float rbx = fminf(bi.z, bj.z), rby = fminf(bi.w, bj.w);
    float wx = fmaxf(rbx - ltx, 0.f), wy = fmaxf(rby - lty, 0.f);
    float inter = wx * wy;
    return inter / (area_i + area_j - inter + 1e-9f) > 0.7f;
}

__global__ __launch_bounds__(256) void mask_kernel(
    const float* __restrict__ topboxes, u64* __restrict__ masks)
{
    int row = blockIdx.x * 8 + (threadIdx.x >> 5);
    int lane = threadIdx.x & 31;
    int seg = row / PRE_N, i = row - seg * PRE_N;
    const float* B = topboxes + (size_t)seg * PRE_N * 4;
    float4 bi = *reinterpret_cast<const float4*>(B + (size_t)i * 4);
    float area_i = (bi.z - bi.x) * (bi.w - bi.y);
    u64* mrow = masks + (size_t)row * 32;
    const int w0 = i >> 6;                 // words below diagonal are all-zero
    for (int w = lane; w < w0; w += 32) mrow[w] = 0ULL;
    for (int w = w0; w < 32; w++) {
        int j0 = w * 64;
        bool p0 = false, p1 = false;
        int j = j0 + lane;
        if (j < PRE_N && j > i)
            p0 = iou_gt(bi, area_i, *reinterpret_cast<const float4*>(B + (size_t)j * 4));
        j = j0 + 32 + lane;
        if (j < PRE_N && j > i)
            p1 = iou_gt(bi, area_i, *reinterpret_cast<const float4*>(B + (size_t)j * 4));
        u32 lo = __ballot_sync(0xFFFFFFFFu, p0);
        u32 hi = __ballot_sync(0xFFFFFFFFu, p1);
        if (lane == 0) mrow[w] = ((u64)hi << 32) | lo;
    }
}

__global__ __launch_bounds__(256) void scan_kernel(
    const float* __restrict__ topscores, const u64* __restrict__ masks, u64* __restrict__ keep)
{
    const int seg = blockIdx.x;
    __shared__ u64 buf[64 * 32];
    const int tid = threadIdx.x;
    const int lane = tid & 31, wid = tid >> 5;

    u64 keepw = 0;
    if (wid == 0) {
        for (int bbit = 0; bbit < 64; bbit++) {
            int i = lane * 64 + bbit;
            if (i < PRE_N && topscores[seg * PRE_N + i] > 0.f) keepw |= 1ULL << bbit;
        }
    }
    const u64* mseg = masks + (size_t)seg * PRE_N * 32;
    for (int c = 0; c < 32; c++) {
        __syncthreads();
        int r0 = c * 64;
        for (int e = tid; e < 64 * 32; e += 256) {
            int rr = e >> 5, wwi = e & 31;
            int row = r0 + rr;
            buf[e] = (row < PRE_N) ? mseg[(size_t)row * 32 + wwi] : 0ULL;
        }
        __syncthreads();
        if (wid == 0) {
            int n = PRE_N - r0; if (n > 64) n = 64;
            for (int r = 0; r < n; r++) {
                u64 kw = __shfl_sync(0xFFFFFFFFu, keepw, c);
                if ((kw >> r) & 1ULL) keepw &= ~buf[r * 32 + lane];
            }
        }
    }
    __syncthreads();
    if (wid == 0) keep[seg * 32 + lane] = keepw;
}

__global__ __launch_bounds__(1024) void post_kernel(
    const float* __restrict__ topscores, const float* __restrict__ topboxes,
    const u64* __restrict__ keepbits, float* __restrict__ out)
{
    const int seg = blockIdx.x;
    __shared__ u64 s[2048];
    const int tid = threadIdx.x;
    for (int i = tid; i < 2048; i += 1024) {
        u64 key;
        if (i < PRE_N) {
            float sc = topscores[seg * PRE_N + i];
            int kept = (int)((keepbits[seg * 32 + (i >> 6)] >> (i & 63)) & 1ULL);
            float ms = kept ? sc : -1.0f;
            key = ((u64)(~ordf(ms)) << 32) | (u32)i;
        } else key = ~0ULL;
        s[i] = key;
    }
    __syncthreads();
    for (int size = 2; size <= 2048; size <<= 1)
        for (int stride = size >> 1; stride >= 1; stride >>= 1) {
            int l = ((tid & ~(stride - 1)) << 1) | (tid & (stride - 1));
            int r = l | stride;
            bool up = ((l & size) == 0);
            u64 a = s[l], bk = s[r];
            if ((a > bk) == up) { s[l] = bk; s[r] = a; }
            __syncthreads();
        }
    if (tid < POST_N) {
        u64 key = s[tid];
        u32 idx = (u32)(key & 0xFFFFFFFFu);
        float sc = unordf(~(u32)(key >> 32));
        float4 bb = *reinterpret_cast<const float4*>(topboxes + ((size_t)seg * PRE_N + idx) * 4);
        float* ob = out + ((size_t)seg * POST_N + tid) * 4;
        ob[0] = bb.x; ob[1] = bb.y; ob[2] = bb.z; ob[3] = bb.w;
        out[BATCH * POST_N * 4 + seg * POST_N + tid] = sc;
    }
}

// ---------------- launch ----------------
extern "C" void kernel_launch(void* const* d_in, const int* in_sizes, int n_in,
                              void* d_out, int out_size)
{
    const float* feat = (const float*)d_in[0];
    const float* W1   = (const float*)d_in[1];
    const float* b1   = (const float*)d_in[2];
    const float* W2   = (const float*)d_in[3];
    const float* b2   = (const float*)d_in[4];
    const float* W3   = (const float*)d_in[5];
    const float* b3   = (const float*)d_in[6];
    float* out = (float*)d_out;

    float *t_ptr, *boxes_ptr, *tb_ptr, *ts_ptr, *U_ptr, *V_ptr, *M_ptr;
    u64 *keys_ptr, *mask_ptr, *keep_ptr;
    cudaGetSymbolAddress((void**)&t_ptr, g_t);
    cudaGetSymbolAddress((void**)&U_ptr, g_U);
    cudaGetSymbolAddress((void**)&V_ptr, g_V);
    cudaGetSymbolAddress((void**)&M_ptr, g_M);
    cudaGetSymbolAddress((void**)&boxes_ptr, g_boxes);
    cudaGetSymbolAddress((void**)&keys_ptr, g_keys);
    cudaGetSymbolAddress((void**)&tb_ptr, g_topboxes);
    cudaGetSymbolAddress((void**)&ts_ptr, g_topscores);
    cudaGetSymbolAddress((void**)&mask_ptr, g_mask);
    cudaGetSymbolAddress((void**)&keep_ptr, g_keep);

    // 1. winograd F(4,3) conv (R15 config)
    wgt_kernel<<<(CMID * CIN + 255) / 256, 256>>>(W1, U_ptr);
    intrans_kernel<<<BATCH * CIN, 128>>>(feat, V_ptr);
    dim3 ggrid((GMW + TM - 1) / TM, CMID / TN, NPT);   // 11 x 4 x 36 = 1584 CTAs
    wino_gemm_kernel<<<ggrid, 256>>>(V_ptr, U_ptr, M_ptr);
    outtrans_kernel<<<(GMW * CMID + 255) / 256, 256>>>(M_ptr, b1, t_ptr);

    // 2. pad keys, then batched head GEMM + decode
    cudaMemsetAsync(keys_ptr, 0xFF, (size_t)BATCH * SEG * sizeof(u64));
    head_kernel<<<(BATCH * HW + HB - 1) / HB, 256>>>(t_ptr, W2, b2, W3, b3, boxes_ptr, keys_ptr);

    // 3. per-segment bitonic sort
    bsortA<<<BATCH * SEG / 4096, 1024>>>(keys_ptr);
    bsortG<<<512, 256>>>(keys_ptr, 8192, 4096);
    bsortF<<<BATCH * SEG / 4096, 1024>>>(keys_ptr, 8192);
    bsortG<<<512, 256>>>(keys_ptr, 16384, 8192);
    bsortG<<<512, 256>>>(keys_ptr, 16384, 4096);
    bsortF<<<BATCH * SEG / 4096, 1024>>>(keys_ptr, 16384);
    bsortG<<<512, 256>>>(keys_ptr, 32768, 16384);
    bsortG<<<512, 256>>>(keys_ptr, 32768, 8192);
    bsortG<<<512, 256>>>(keys_ptr, 32768, 4096);
    bsortF<<<BATCH * SEG / 4096, 1024>>>(keys_ptr, 32768);

    // 4-6. gather, NMS, output
    gather_kernel<<<(BATCH * PRE_N + 255) / 256, 256>>>(keys_ptr, boxes_ptr, tb_ptr, ts_ptr);
    mask_kernel<<<BATCH * PRE_N / 8, 256>>>(tb_ptr, mask_ptr);
    scan_kernel<<<BATCH, 256>>>(ts_ptr, mask_ptr, keep_ptr);
    post_kernel<<<BATCH, 1024>>>(ts_ptr, tb_ptr, keep_ptr, out);
}